// round 7
// baseline (speedup 1.0000x reference)
#include <cuda_runtime.h>
#include <math.h>

typedef unsigned long long ull;

// LureSystem on GB300 — R5.
// Fused e-phase: e = (C@A)x + (C@B+D)d + (C@B2+D12)w shares act vector with
// x-update -> one 40-row mm. 16 groups x 8-CTA clusters, 640 threads.
// Exchange via L2 st.cg/ld.cg + barrier.cluster (release/acquire, no fence).

#define NSTEPS 2048
#define RANKS 8
#define GROUPS 16
#define BT 16
#define THREADS 640

#define S_ACT 584           // [x(256)|d(64)|w(256)] padded; %32==8 -> btile banks 8*bt
#define PARW 576            // w-phase per-chunk partial stride (16*36)
#define PARX 704            // xe-phase per-chunk partial stride (16*44)

// SMEM float offsets
#define OFF_W1T 0           // [320][32]  [C2|D21]^T rows rw..rw+31
#define OFF_W2T 10240       // [576][40]  rows 0-31: [A|B|B2]^T ; rows 32-39: fused E^T
#define OFF_ACT 33280       // [16][584]
#define OFF_PAR 42624       // max(20*576, 16*704) = 11520
#define SMEM_FLOATS 54144   // 216576 bytes

#define E_SIZE (256 * NSTEPS * 64)
#define BASE_X E_SIZE
#define BASE_W (E_SIZE + 256 * 256)

__device__ float g_EW[64 * 576];             // fused e-weights [row][ x|d|w cols ]
__device__ float g_wbuf[GROUPS * BT * 256];
__device__ float g_xbuf[GROUPS * BT * 256];

__device__ __forceinline__ void cluster_sync() {
    // arrive defaults to .release, wait to .acquire: orders st.cg -> ld.cg in cluster
    asm volatile("barrier.cluster.arrive.aligned;" ::: "memory");
    asm volatile("barrier.cluster.wait.aligned;" ::: "memory");
}

__device__ __forceinline__ void fma2(ull& acc, ull m, ull a) {
    asm("fma.rn.f32x2 %0, %1, %2, %0;" : "+l"(acc) : "l"(m), "l"(a));
}
__device__ __forceinline__ ull pack2(float x) {
    ull r; asm("mov.b64 %0, {%1, %1};" : "=l"(r) : "f"(x)); return r;
}

// 4 rows x 4 batches (b = btile + 4*kk) over K-chunk of 4*L4, f32x2 FMAs.
template <int L4, int WS, int BS>
__device__ __forceinline__ void mmT(const float* __restrict__ WT,
                                    const float* __restrict__ Act,
                                    float* __restrict__ P) {
    ull a01[4] = {0ull, 0ull, 0ull, 0ull};
    ull a23[4] = {0ull, 0ull, 0ull, 0ull};
#pragma unroll
    for (int j4 = 0; j4 < L4; j4++) {
        float av[4][4];
#pragma unroll
        for (int kk = 0; kk < 4; kk++) {
            float4 t4 = *reinterpret_cast<const float4*>(Act + kk * (4 * S_ACT) + 4 * j4);
            av[kk][0] = t4.x; av[kk][1] = t4.y; av[kk][2] = t4.z; av[kk][3] = t4.w;
        }
#pragma unroll
        for (int jj = 0; jj < 4; jj++) {
            ulonglong2 m = *reinterpret_cast<const ulonglong2*>(WT + (4 * j4 + jj) * WS);
#pragma unroll
            for (int kk = 0; kk < 4; kk++) {
                ull aa = pack2(av[kk][jj]);
                fma2(a01[kk], m.x, aa);
                fma2(a23[kk], m.y, aa);
            }
        }
    }
#pragma unroll
    for (int kk = 0; kk < 4; kk++)
        *reinterpret_cast<ulonglong2*>(P + kk * (4 * BS)) = make_ulonglong2(a01[kk], a23[kk]);
}

// ---- pre-kernel: build fused e-weights EW = [C@A | C@B + D | C@B2 + D12] ----
__global__ void fuse_kernel(const float* __restrict__ A, const float* __restrict__ B,
                            const float* __restrict__ B2, const float* __restrict__ C,
                            const float* __restrict__ D, const float* __restrict__ D12) {
    __shared__ float c[256];
    int i = blockIdx.x;
    for (int idx = threadIdx.x; idx < 256; idx += blockDim.x) c[idx] = C[i * 256 + idx];
    __syncthreads();
    for (int j = threadIdx.x; j < 576; j += blockDim.x) {
        float s = 0.f;
        if (j < 256) {
            for (int kk = 0; kk < 256; kk++) s = fmaf(c[kk], A[kk * 256 + j], s);
        } else if (j < 320) {
            int jj = j - 256;
            for (int kk = 0; kk < 256; kk++) s = fmaf(c[kk], B[kk * 64 + jj], s);
            s += D[i * 64 + jj];
        } else {
            int jj = j - 320;
            for (int kk = 0; kk < 256; kk++) s = fmaf(c[kk], B2[kk * 256 + jj], s);
            s += D12[i * 256 + jj];
        }
        g_EW[i * 576 + j] = s;
    }
}

__global__ void __cluster_dims__(RANKS, 1, 1) __launch_bounds__(THREADS, 1)
lure_kernel(const float* __restrict__ dseq,
            const float* __restrict__ x0,
            const float* __restrict__ Amat,
            const float* __restrict__ Bmat,
            const float* __restrict__ B2mat,
            const float* __restrict__ C2mat,
            const float* __restrict__ D21mat,
            float* __restrict__ out) {
    extern __shared__ float smem[];
    float* sW1T = smem + OFF_W1T;
    float* sW2T = smem + OFF_W2T;
    float* sAct = smem + OFF_ACT;
    float* sPar = smem + OFF_PAR;

    const int t = threadIdx.x;
    const int g = blockIdx.x >> 3;
    const int r = blockIdx.x & 7;
    const int rw = r * 32;
    const int re = r * 8;

    // ---- resident weights (transposed [K][row]) ----
    for (int idx = t; idx < 320 * 32; idx += THREADS) {
        int row = idx & 31, j = idx >> 5;
        float v = (j < 256) ? C2mat[(rw + row) * 256 + j]
                            : D21mat[(rw + row) * 64 + (j - 256)];
        sW1T[j * 32 + row] = v;
    }
    for (int idx = t; idx < 576 * 40; idx += THREADS) {
        int row = idx % 40, j = idx / 40;
        float v;
        if (row < 32) {
            int gr = rw + row;
            if (j < 256)      v = Amat[gr * 256 + j];
            else if (j < 320) v = Bmat[gr * 64 + (j - 256)];
            else              v = B2mat[gr * 256 + (j - 320)];
        } else {
            v = g_EW[(re + row - 32) * 576 + j];
        }
        sW2T[j * 40 + row] = v;
    }
    for (int idx = t; idx < BT * 256; idx += THREADS) {
        int b = idx >> 8, col = idx & 255;
        sAct[b * S_ACT + col] = x0[(g * BT + b) * 256 + col];
    }
    for (int idx = t; idx < BT * 64; idx += THREADS) {
        int b = idx >> 6, j = idx & 63;
        sAct[b * S_ACT + 256 + j] = dseq[(size_t)(g * BT + b) * (NSTEPS * 64) + j];
    }

    // work decomposition
    const int lane = t & 31, warp = t >> 5;
    const int btw = lane >> 3, row0w = (lane & 7) * 4, j0w = warp * 16;   // w-phase
    const int tl = t % 40, chunkx = t / 40;
    const int btx = tl / 10, row0x = (tl % 10) * 4, j0x = chunkx * 36;    // xe-phase
    const int rb = t >> 5, rr = t & 31;          // w reduce (t<512)
    const int xb = t / 40, xr = t % 40;          // xe reduce

    float* gw = g_wbuf + g * (BT * 256);
    float* gx = g_xbuf + g * (BT * 256);

    float dpre0, dpre1;
    const int d0b = t >> 6, d0j = t & 63;
    const int i1 = t + 640;
    const int d1b = i1 >> 6, d1j = i1 & 63;

    __syncthreads();

    for (int k = 0; k < NSTEPS; ++k) {
        // prefetch d_{k+1}
        int kp = (k + 1 < NSTEPS) ? (k + 1) : (NSTEPS - 1);
        dpre0 = dseq[(size_t)(g * BT + d0b) * (NSTEPS * 64) + (size_t)kp * 64 + d0j];
        if (i1 < 1024)
            dpre1 = dseq[(size_t)(g * BT + d1b) * (NSTEPS * 64) + (size_t)kp * 64 + d1j];

        // ---- w-phase: 32 rows, K=320, chunk=warp (20 x 16) ----
        mmT<4, 32, 36>(sW1T + j0w * 32 + row0w,
                       sAct + btw * S_ACT + j0w,
                       sPar + warp * PARW + btw * 36 + row0w);
        __syncthreads();
        if (t < 512) {
            float s = 0.f;
#pragma unroll
            for (int c = 0; c < 20; c++) s += sPar[c * PARW + rb * 36 + rr];
            __stcg(&gw[rb * 256 + rw + rr], tanhf(s));
        }
        cluster_sync();
#pragma unroll
        for (int u = 0; u < 7; ++u) {
            int idx = t + u * THREADS;
            if (idx < 4096) {
                int b = idx >> 8, j = idx & 255;
                sAct[b * S_ACT + 320 + j] = __ldcg(&gw[b * 256 + j]);
            }
        }
        __syncthreads();

        // ---- xe-phase: 40 rows (32 x' + 8 e), K=576, 16 chunks x 36 ----
        mmT<9, 40, 44>(sW2T + j0x * 40 + row0x,
                       sAct + btx * S_ACT + j0x,
                       sPar + chunkx * PARX + btx * 44 + row0x);
        __syncthreads();
        {
            float s = 0.f;
#pragma unroll
            for (int c = 0; c < 16; c++) s += sPar[c * PARX + xb * 44 + xr];
            if (xr < 32)
                __stcg(&gx[xb * 256 + rw + xr], s);
            else
                out[(size_t)(g * BT + xb) * (NSTEPS * 64) + (size_t)k * 64 + re + (xr - 32)] = s;
            // commit prefetched d_{k+1} (d region free after xe-mm barrier)
            sAct[d0b * S_ACT + 256 + d0j] = dpre0;
            if (i1 < 1024) sAct[d1b * S_ACT + 256 + d1j] = dpre1;
        }
        cluster_sync();
#pragma unroll
        for (int u = 0; u < 7; ++u) {
            int idx = t + u * THREADS;
            if (idx < 4096) {
                int b = idx >> 8, j = idx & 255;
                sAct[b * S_ACT + j] = __ldcg(&gx[b * 256 + j]);
            }
        }
        __syncthreads();
    }

    // final states: x_final from act x-part, w_{N-1} from act w-part
    if (t < 512) {
        int b = t >> 5, row = t & 31;
        out[BASE_X + (size_t)(g * BT + b) * 256 + rw + row] = sAct[b * S_ACT + rw + row];
        out[BASE_W + (size_t)(g * BT + b) * 256 + rw + row] = sAct[b * S_ACT + 320 + rw + row];
    }
}

extern "C" void kernel_launch(void* const* d_in, const int* in_sizes, int n_in,
                              void* d_out, int out_size) {
    (void)in_sizes; (void)n_in; (void)out_size;
    const float* dseq = (const float*)d_in[0];
    const float* x0   = (const float*)d_in[1];
    const float* A    = (const float*)d_in[2];
    const float* B    = (const float*)d_in[3];
    const float* B2   = (const float*)d_in[4];
    const float* C    = (const float*)d_in[5];
    const float* D    = (const float*)d_in[6];
    const float* D12  = (const float*)d_in[7];
    const float* C2   = (const float*)d_in[8];
    const float* D21  = (const float*)d_in[9];
    float* out = (float*)d_out;

    fuse_kernel<<<64, 256>>>(A, B, B2, C, D, D12);

    const size_t smem_bytes = (size_t)SMEM_FLOATS * sizeof(float);
    cudaFuncSetAttribute(lure_kernel, cudaFuncAttributeMaxDynamicSharedMemorySize,
                         (int)smem_bytes);
    lure_kernel<<<GROUPS * RANKS, THREADS, smem_bytes>>>(dseq, x0, A, B, B2,
                                                         C2, D21, out);
}

// round 8
// speedup vs baseline: 1.0038x; 1.0038x over previous
#include <cuda_runtime.h>
#include <math.h>

typedef unsigned long long ull;

// LureSystem on GB300 — R5.
// Fused e-phase: e = (C@A)x + (C@B+D)d + (C@B2+D12)w shares act vector with
// x-update -> one 40-row mm. 16 groups x 8-CTA clusters, 640 threads.
// Exchange via L2 st.cg/ld.cg + barrier.cluster (release/acquire, no fence).

#define NSTEPS 2048
#define RANKS 8
#define GROUPS 16
#define BT 16
#define THREADS 640

#define S_ACT 584           // [x(256)|d(64)|w(256)] padded; %32==8 -> btile banks 8*bt
#define PARW 576            // w-phase per-chunk partial stride (16*36)
#define PARX 704            // xe-phase per-chunk partial stride (16*44)

// SMEM float offsets
#define OFF_W1T 0           // [320][32]  [C2|D21]^T rows rw..rw+31
#define OFF_W2T 10240       // [576][40]  rows 0-31: [A|B|B2]^T ; rows 32-39: fused E^T
#define OFF_ACT 33280       // [16][584]
#define OFF_PAR 42624       // max(20*576, 16*704) = 11520
#define SMEM_FLOATS 54144   // 216576 bytes

#define E_SIZE (256 * NSTEPS * 64)
#define BASE_X E_SIZE
#define BASE_W (E_SIZE + 256 * 256)

__device__ float g_EW[64 * 576];             // fused e-weights [row][ x|d|w cols ]
__device__ float g_wbuf[GROUPS * BT * 256];
__device__ float g_xbuf[GROUPS * BT * 256];

__device__ __forceinline__ void cluster_sync() {
    // arrive defaults to .release, wait to .acquire: orders st.cg -> ld.cg in cluster
    asm volatile("barrier.cluster.arrive.aligned;" ::: "memory");
    asm volatile("barrier.cluster.wait.aligned;" ::: "memory");
}

__device__ __forceinline__ void fma2(ull& acc, ull m, ull a) {
    asm("fma.rn.f32x2 %0, %1, %2, %0;" : "+l"(acc) : "l"(m), "l"(a));
}
__device__ __forceinline__ ull pack2(float x) {
    ull r; asm("mov.b64 %0, {%1, %1};" : "=l"(r) : "f"(x)); return r;
}

// 4 rows x 4 batches (b = btile + 4*kk) over K-chunk of 4*L4, f32x2 FMAs.
template <int L4, int WS, int BS>
__device__ __forceinline__ void mmT(const float* __restrict__ WT,
                                    const float* __restrict__ Act,
                                    float* __restrict__ P) {
    ull a01[4] = {0ull, 0ull, 0ull, 0ull};
    ull a23[4] = {0ull, 0ull, 0ull, 0ull};
#pragma unroll
    for (int j4 = 0; j4 < L4; j4++) {
        float av[4][4];
#pragma unroll
        for (int kk = 0; kk < 4; kk++) {
            float4 t4 = *reinterpret_cast<const float4*>(Act + kk * (4 * S_ACT) + 4 * j4);
            av[kk][0] = t4.x; av[kk][1] = t4.y; av[kk][2] = t4.z; av[kk][3] = t4.w;
        }
#pragma unroll
        for (int jj = 0; jj < 4; jj++) {
            ulonglong2 m = *reinterpret_cast<const ulonglong2*>(WT + (4 * j4 + jj) * WS);
#pragma unroll
            for (int kk = 0; kk < 4; kk++) {
                ull aa = pack2(av[kk][jj]);
                fma2(a01[kk], m.x, aa);
                fma2(a23[kk], m.y, aa);
            }
        }
    }
#pragma unroll
    for (int kk = 0; kk < 4; kk++)
        *reinterpret_cast<ulonglong2*>(P + kk * (4 * BS)) = make_ulonglong2(a01[kk], a23[kk]);
}

// ---- pre-kernel: build fused e-weights EW = [C@A | C@B + D | C@B2 + D12] ----
__global__ void fuse_kernel(const float* __restrict__ A, const float* __restrict__ B,
                            const float* __restrict__ B2, const float* __restrict__ C,
                            const float* __restrict__ D, const float* __restrict__ D12) {
    __shared__ float c[256];
    int i = blockIdx.x;
    for (int idx = threadIdx.x; idx < 256; idx += blockDim.x) c[idx] = C[i * 256 + idx];
    __syncthreads();
    for (int j = threadIdx.x; j < 576; j += blockDim.x) {
        float s = 0.f;
        if (j < 256) {
            for (int kk = 0; kk < 256; kk++) s = fmaf(c[kk], A[kk * 256 + j], s);
        } else if (j < 320) {
            int jj = j - 256;
            for (int kk = 0; kk < 256; kk++) s = fmaf(c[kk], B[kk * 64 + jj], s);
            s += D[i * 64 + jj];
        } else {
            int jj = j - 320;
            for (int kk = 0; kk < 256; kk++) s = fmaf(c[kk], B2[kk * 256 + jj], s);
            s += D12[i * 256 + jj];
        }
        g_EW[i * 576 + j] = s;
    }
}

__global__ void __cluster_dims__(RANKS, 1, 1) __launch_bounds__(THREADS, 1)
lure_kernel(const float* __restrict__ dseq,
            const float* __restrict__ x0,
            const float* __restrict__ Amat,
            const float* __restrict__ Bmat,
            const float* __restrict__ B2mat,
            const float* __restrict__ C2mat,
            const float* __restrict__ D21mat,
            float* __restrict__ out) {
    extern __shared__ float smem[];
    float* sW1T = smem + OFF_W1T;
    float* sW2T = smem + OFF_W2T;
    float* sAct = smem + OFF_ACT;
    float* sPar = smem + OFF_PAR;

    const int t = threadIdx.x;
    const int g = blockIdx.x >> 3;
    const int r = blockIdx.x & 7;
    const int rw = r * 32;
    const int re = r * 8;

    // ---- resident weights (transposed [K][row]) ----
    for (int idx = t; idx < 320 * 32; idx += THREADS) {
        int row = idx & 31, j = idx >> 5;
        float v = (j < 256) ? C2mat[(rw + row) * 256 + j]
                            : D21mat[(rw + row) * 64 + (j - 256)];
        sW1T[j * 32 + row] = v;
    }
    for (int idx = t; idx < 576 * 40; idx += THREADS) {
        int row = idx % 40, j = idx / 40;
        float v;
        if (row < 32) {
            int gr = rw + row;
            if (j < 256)      v = Amat[gr * 256 + j];
            else if (j < 320) v = Bmat[gr * 64 + (j - 256)];
            else              v = B2mat[gr * 256 + (j - 320)];
        } else {
            v = g_EW[(re + row - 32) * 576 + j];
        }
        sW2T[j * 40 + row] = v;
    }
    for (int idx = t; idx < BT * 256; idx += THREADS) {
        int b = idx >> 8, col = idx & 255;
        sAct[b * S_ACT + col] = x0[(g * BT + b) * 256 + col];
    }
    for (int idx = t; idx < BT * 64; idx += THREADS) {
        int b = idx >> 6, j = idx & 63;
        sAct[b * S_ACT + 256 + j] = dseq[(size_t)(g * BT + b) * (NSTEPS * 64) + j];
    }

    // work decomposition
    const int lane = t & 31, warp = t >> 5;
    const int btw = lane >> 3, row0w = (lane & 7) * 4, j0w = warp * 16;   // w-phase
    const int tl = t % 40, chunkx = t / 40;
    const int btx = tl / 10, row0x = (tl % 10) * 4, j0x = chunkx * 36;    // xe-phase
    const int rb = t >> 5, rr = t & 31;          // w reduce (t<512)
    const int xb = t / 40, xr = t % 40;          // xe reduce

    float* gw = g_wbuf + g * (BT * 256);
    float* gx = g_xbuf + g * (BT * 256);

    float dpre0, dpre1;
    const int d0b = t >> 6, d0j = t & 63;
    const int i1 = t + 640;
    const int d1b = i1 >> 6, d1j = i1 & 63;

    __syncthreads();

    for (int k = 0; k < NSTEPS; ++k) {
        // prefetch d_{k+1}
        int kp = (k + 1 < NSTEPS) ? (k + 1) : (NSTEPS - 1);
        dpre0 = dseq[(size_t)(g * BT + d0b) * (NSTEPS * 64) + (size_t)kp * 64 + d0j];
        if (i1 < 1024)
            dpre1 = dseq[(size_t)(g * BT + d1b) * (NSTEPS * 64) + (size_t)kp * 64 + d1j];

        // ---- w-phase: 32 rows, K=320, chunk=warp (20 x 16) ----
        mmT<4, 32, 36>(sW1T + j0w * 32 + row0w,
                       sAct + btw * S_ACT + j0w,
                       sPar + warp * PARW + btw * 36 + row0w);
        __syncthreads();
        if (t < 512) {
            float s = 0.f;
#pragma unroll
            for (int c = 0; c < 20; c++) s += sPar[c * PARW + rb * 36 + rr];
            __stcg(&gw[rb * 256 + rw + rr], tanhf(s));
        }
        cluster_sync();
#pragma unroll
        for (int u = 0; u < 7; ++u) {
            int idx = t + u * THREADS;
            if (idx < 4096) {
                int b = idx >> 8, j = idx & 255;
                sAct[b * S_ACT + 320 + j] = __ldcg(&gw[b * 256 + j]);
            }
        }
        __syncthreads();

        // ---- xe-phase: 40 rows (32 x' + 8 e), K=576, 16 chunks x 36 ----
        mmT<9, 40, 44>(sW2T + j0x * 40 + row0x,
                       sAct + btx * S_ACT + j0x,
                       sPar + chunkx * PARX + btx * 44 + row0x);
        __syncthreads();
        {
            float s = 0.f;
#pragma unroll
            for (int c = 0; c < 16; c++) s += sPar[c * PARX + xb * 44 + xr];
            if (xr < 32)
                __stcg(&gx[xb * 256 + rw + xr], s);
            else
                out[(size_t)(g * BT + xb) * (NSTEPS * 64) + (size_t)k * 64 + re + (xr - 32)] = s;
            // commit prefetched d_{k+1} (d region free after xe-mm barrier)
            sAct[d0b * S_ACT + 256 + d0j] = dpre0;
            if (i1 < 1024) sAct[d1b * S_ACT + 256 + d1j] = dpre1;
        }
        cluster_sync();
#pragma unroll
        for (int u = 0; u < 7; ++u) {
            int idx = t + u * THREADS;
            if (idx < 4096) {
                int b = idx >> 8, j = idx & 255;
                sAct[b * S_ACT + j] = __ldcg(&gx[b * 256 + j]);
            }
        }
        __syncthreads();
    }

    // final states: x_final from act x-part, w_{N-1} from act w-part
    if (t < 512) {
        int b = t >> 5, row = t & 31;
        out[BASE_X + (size_t)(g * BT + b) * 256 + rw + row] = sAct[b * S_ACT + rw + row];
        out[BASE_W + (size_t)(g * BT + b) * 256 + rw + row] = sAct[b * S_ACT + 320 + rw + row];
    }
}

extern "C" void kernel_launch(void* const* d_in, const int* in_sizes, int n_in,
                              void* d_out, int out_size) {
    (void)in_sizes; (void)n_in; (void)out_size;
    const float* dseq = (const float*)d_in[0];
    const float* x0   = (const float*)d_in[1];
    const float* A    = (const float*)d_in[2];
    const float* B    = (const float*)d_in[3];
    const float* B2   = (const float*)d_in[4];
    const float* C    = (const float*)d_in[5];
    const float* D    = (const float*)d_in[6];
    const float* D12  = (const float*)d_in[7];
    const float* C2   = (const float*)d_in[8];
    const float* D21  = (const float*)d_in[9];
    float* out = (float*)d_out;

    fuse_kernel<<<64, 256>>>(A, B, B2, C, D, D12);

    const size_t smem_bytes = (size_t)SMEM_FLOATS * sizeof(float);
    cudaFuncSetAttribute(lure_kernel, cudaFuncAttributeMaxDynamicSharedMemorySize,
                         (int)smem_bytes);
    lure_kernel<<<GROUPS * RANKS, THREADS, smem_bytes>>>(dseq, x0, A, B, B2,
                                                         C2, D21, out);
}